// round 16
// baseline (speedup 1.0000x reference)
#include <cuda_runtime.h>
#include <cuda_fp16.h>
#include <cstdint>

// Problem constants: B=2, T=8192, D=2048, W=128
#define BATCH 2
#define SEQ   8192
#define DIM   2048
#define WIN   128
#define NBLK  64
#define ROWS  16384
#define QKVN  6144

// Scratch (device globals: the sanctioned alloc-free workaround)
__device__ __half g_qkv[(size_t)ROWS * QKVN];
__device__ __half g_attn[(size_t)BATCH * NBLK * 128 * 256];
__device__ __half g_ao[(size_t)ROWS * DIM];
__device__ __half g_wah[(size_t)QKVN * DIM];
__device__ __half g_woh[(size_t)DIM * DIM];

// ---------------------------------------------------------------------------
// helpers
// ---------------------------------------------------------------------------
__device__ __forceinline__ uint32_t smem_u32(const void* p) {
    uint32_t a;
    asm("{ .reg .u64 t; cvta.to.shared.u64 t, %1; cvt.u32.u64 %0, t; }" : "=r"(a) : "l"(p));
    return a;
}

__device__ __forceinline__ void mma_f16(float& d0, float& d1, float& d2, float& d3,
                                        uint32_t a0, uint32_t a1, uint32_t a2, uint32_t a3,
                                        uint32_t b0, uint32_t b1) {
    asm volatile(
        "mma.sync.aligned.m16n8k16.row.col.f32.f16.f16.f32 "
        "{%0,%1,%2,%3}, {%4,%5,%6,%7}, {%8,%9}, {%0,%1,%2,%3};\n"
        : "+f"(d0), "+f"(d1), "+f"(d2), "+f"(d3)
        : "r"(a0), "r"(a1), "r"(a2), "r"(a3), "r"(b0), "r"(b1));
}

#define LDSM_X4(r0, r1, r2, r3, addr)                                          \
    asm volatile("ldmatrix.sync.aligned.m8n8.x4.shared.b16 {%0,%1,%2,%3}, [%4];" \
                 : "=r"(r0), "=r"(r1), "=r"(r2), "=r"(r3) : "r"(addr))
#define LDSM_X4T(r0, r1, r2, r3, addr)                                         \
    asm volatile("ldmatrix.sync.aligned.m8n8.x4.trans.shared.b16 {%0,%1,%2,%3}, [%4];" \
                 : "=r"(r0), "=r"(r1), "=r"(r2), "=r"(r3) : "r"(addr))

#define CP_ASYNC16(dst, src)                                                   \
    asm volatile("cp.async.cg.shared.global [%0], [%1], 16;"                   \
                 :: "r"(dst), "l"(src) : "memory")
#define CP_COMMIT() asm volatile("cp.async.commit_group;" ::: "memory")
#define CP_WAIT1()  asm volatile("cp.async.wait_group 1;" ::: "memory")

#define STS64(addr, u0, u1)                                                    \
    asm volatile("st.shared.v2.b32 [%0], {%1,%2};" :: "r"(addr), "r"(u0), "r"(u1) : "memory")

// ---------------------------------------------------------------------------
// GEMM geometry (R8, proven best): CTA 64x128, K-tile 64, 2 stages, 4 CTAs/SM.
#define ROW_B     144
#define G8_MAT_A  9216
#define G8_STAGE  27648
#define G8_SMEM   (2 * G8_STAGE)

// sim geometry: 128x128 tile, 3 stages
#define SI_MAT_B  18432
#define SI_STAGE  36864
#define SI_SMEM   (3 * SI_STAGE)

// PV geometry (R12): CTA 128(M) x 128(N), K-tile 32, 3 stages.
#define PV_ROWA   80
#define PV_AMAT   10240
#define PV_ROWV   272
#define PV_VMAT   8704
#define PV_STG    (PV_AMAT + PV_VMAT)
#define PV_SMEM   (3 * PV_STG)

// ---------------------------------------------------------------------------
// fp16 NT GEMM (proven, for gemm2): CTA 64x128, 4 warps, 2-stage, 4 CTAs/SM.
// ---------------------------------------------------------------------------
__global__ __launch_bounds__(128, 4)
void gemm_h_kernel(const __half* __restrict__ A, const __half* __restrict__ B,
                   void* __restrict__ Cout, int lda, int ldb, int N, int K,
                   int out_half) {
    extern __shared__ __align__(128) char smem[];
    const uint32_t smem_base = smem_u32(smem);

    const int m_tile = blockIdx.x;
    const int n_tile = blockIdx.y;

    const int tid  = threadIdx.x;
    const int warp = tid >> 5, lane = tid & 31;
    const int wm = (warp & 1) << 5;
    const int wn = (warp >> 1) << 6;
    const int g  = lane >> 2, tg = lane & 3;
    const int lr = tid >> 3;
    const int c4 = tid & 7;

    const int sel = lane >> 3;
    const int i8  = lane & 7;
    uint32_t a_addr[2], b_addr[4];
    #pragma unroll
    for (int mf = 0; mf < 2; mf++) {
        const int row = wm + 16 * mf + (sel & 1) * 8 + i8;
        a_addr[mf] = smem_base + (uint32_t)row * ROW_B + (sel >> 1) * 16;
    }
    #pragma unroll
    for (int np = 0; np < 4; np++) {
        const int row = wn + np * 16 + (sel >> 1) * 8 + i8;
        b_addr[np] = smem_base + G8_MAT_A + (uint32_t)row * ROW_B + (sel & 1) * 16;
    }

    const __half* Ab = A + (size_t)(m_tile * 64 + lr) * lda + c4 * 8;
    const __half* Bb = B + (size_t)(n_tile * 128 + lr) * ldb + c4 * 8;
    const uint32_t dA = smem_base + (uint32_t)lr * ROW_B + c4 * 16;
    const uint32_t dB = smem_base + G8_MAT_A + (uint32_t)lr * ROW_B + c4 * 16;

    float acc[2][8][4];
    #pragma unroll
    for (int i = 0; i < 2; i++)
        #pragma unroll
        for (int j = 0; j < 8; j++)
            #pragma unroll
            for (int q = 0; q < 4; q++) acc[i][j][q] = 0.f;

    const int NT = K >> 6;

    #pragma unroll
    for (int s = 0; s < 2; s++) {
        const uint32_t o = (uint32_t)s * G8_STAGE;
        const __half* An = Ab + s * 64;
        const __half* Bn = Bb + s * 64;
        #pragma unroll
        for (int j = 0; j < 4; j++)
            CP_ASYNC16(dA + o + j * (16 * ROW_B), An + (size_t)(j * 16) * lda);
        #pragma unroll
        for (int j = 0; j < 8; j++)
            CP_ASYNC16(dB + o + j * (16 * ROW_B), Bn + (size_t)(j * 16) * ldb);
        CP_COMMIT();
    }

    uint32_t af[2][4], bf[4][4];

    for (int it = 0; it < NT; it++) {
        CP_WAIT1();
        __syncthreads();

        const uint32_t so = (uint32_t)(it & 1) * G8_STAGE;
        #pragma unroll
        for (int ks = 0; ks < 4; ks++) {
            const uint32_t ko = so + (uint32_t)ks * 32;
            #pragma unroll
            for (int mf = 0; mf < 2; mf++)
                LDSM_X4(af[mf][0], af[mf][1], af[mf][2], af[mf][3], a_addr[mf] + ko);
            #pragma unroll
            for (int np = 0; np < 4; np++)
                LDSM_X4(bf[np][0], bf[np][1], bf[np][2], bf[np][3], b_addr[np] + ko);
            #pragma unroll
            for (int mf = 0; mf < 2; mf++)
                #pragma unroll
                for (int np = 0; np < 4; np++) {
                    mma_f16(acc[mf][2 * np + 0][0], acc[mf][2 * np + 0][1],
                            acc[mf][2 * np + 0][2], acc[mf][2 * np + 0][3],
                            af[mf][0], af[mf][1], af[mf][2], af[mf][3],
                            bf[np][0], bf[np][1]);
                    mma_f16(acc[mf][2 * np + 1][0], acc[mf][2 * np + 1][1],
                            acc[mf][2 * np + 1][2], acc[mf][2 * np + 1][3],
                            af[mf][0], af[mf][1], af[mf][2], af[mf][3],
                            bf[np][2], bf[np][3]);
                }
        }
        __syncthreads();

        if (it + 2 < NT) {
            const uint32_t o = (uint32_t)(it & 1) * G8_STAGE;
            const __half* An = Ab + (it + 2) * 64;
            const __half* Bn = Bb + (it + 2) * 64;
            #pragma unroll
            for (int j = 0; j < 4; j++)
                CP_ASYNC16(dA + o + j * (16 * ROW_B), An + (size_t)(j * 16) * lda);
            #pragma unroll
            for (int j = 0; j < 8; j++)
                CP_ASYNC16(dB + o + j * (16 * ROW_B), Bn + (size_t)(j * 16) * ldb);
        }
        CP_COMMIT();
    }

    #pragma unroll
    for (int mf = 0; mf < 2; mf++) {
        #pragma unroll
        for (int nf = 0; nf < 8; nf++) {
            const int row = m_tile * 64 + wm + mf * 16 + g;
            const int col = n_tile * 128 + wn + nf * 8 + (tg << 1);
            if (out_half) {
                __half* C = (__half*)Cout;
                *(__half2*)(C + (size_t)row * N + col) =
                    __floats2half2_rn(acc[mf][nf][0], acc[mf][nf][1]);
                *(__half2*)(C + (size_t)(row + 8) * N + col) =
                    __floats2half2_rn(acc[mf][nf][2], acc[mf][nf][3]);
            } else {
                float* C = (float*)Cout;
                *(float2*)(C + (size_t)row * N + col) =
                    make_float2(acc[mf][nf][0], acc[mf][nf][1]);
                *(float2*)(C + (size_t)(row + 8) * N + col) =
                    make_float2(acc[mf][nf][2], acc[mf][nf][3]);
            }
        }
    }
}

// ---------------------------------------------------------------------------
// fp32-A NT GEMM (gemm1): A is fp32 (x), converted in-kernel to the same fp16
// smem layout; B is fp16 via cp.async. Saves the separate x convert pass.
// ---------------------------------------------------------------------------
__global__ __launch_bounds__(128, 4)
void gemm_h32a_kernel(const float* __restrict__ A, const __half* __restrict__ B,
                      __half* __restrict__ C, int lda, int ldb, int N, int K) {
    extern __shared__ __align__(128) char smem[];
    const uint32_t smem_base = smem_u32(smem);

    const int m_tile = blockIdx.x;
    const int n_tile = blockIdx.y;

    const int tid  = threadIdx.x;
    const int warp = tid >> 5, lane = tid & 31;
    const int wm = (warp & 1) << 5;
    const int wn = (warp >> 1) << 6;
    const int g  = lane >> 2, tg = lane & 3;
    const int lr = tid >> 3;
    const int c4 = tid & 7;

    // A staging: thread -> (row tid>>1, 32-float half tid&1)
    const int ar = tid >> 1;          // 0..63
    const int ac = (tid & 1) * 32;    // float column offset

    const int sel = lane >> 3;
    const int i8  = lane & 7;
    uint32_t a_addr[2], b_addr[4];
    #pragma unroll
    for (int mf = 0; mf < 2; mf++) {
        const int row = wm + 16 * mf + (sel & 1) * 8 + i8;
        a_addr[mf] = smem_base + (uint32_t)row * ROW_B + (sel >> 1) * 16;
    }
    #pragma unroll
    for (int np = 0; np < 4; np++) {
        const int row = wn + np * 16 + (sel >> 1) * 8 + i8;
        b_addr[np] = smem_base + G8_MAT_A + (uint32_t)row * ROW_B + (sel & 1) * 16;
    }

    const float* As = A + (size_t)(m_tile * 64 + ar) * lda + ac;
    const uint32_t dAs = smem_base + (uint32_t)ar * ROW_B + ac * 2;
    const __half* Bb = B + (size_t)(n_tile * 128 + lr) * ldb + c4 * 8;
    const uint32_t dB = smem_base + G8_MAT_A + (uint32_t)lr * ROW_B + c4 * 16;

    float acc[2][8][4];
    #pragma unroll
    for (int i = 0; i < 2; i++)
        #pragma unroll
        for (int j = 0; j < 8; j++)
            #pragma unroll
            for (int q = 0; q < 4; q++) acc[i][j][q] = 0.f;

    const int NT = K >> 6;

    // A stage: LDG fp32 -> cvt -> STS fp16 (identical layout to cp.async path)
    auto stage_a = [&](int it, uint32_t o) {
        const float* src = As + it * 64;
        #pragma unroll
        for (int j = 0; j < 8; j++) {
            float4 v = *(const float4*)(src + j * 4);
            __half2 h0 = __floats2half2_rn(v.x, v.y);
            __half2 h1 = __floats2half2_rn(v.z, v.w);
            STS64(dAs + o + j * 8,
                  *(uint32_t*)&h0, *(uint32_t*)&h1);
        }
    };

    #pragma unroll
    for (int s = 0; s < 2; s++) {
        const uint32_t o = (uint32_t)s * G8_STAGE;
        stage_a(s, o);
        const __half* Bn = Bb + s * 64;
        #pragma unroll
        for (int j = 0; j < 8; j++)
            CP_ASYNC16(dB + o + j * (16 * ROW_B), Bn + (size_t)(j * 16) * ldb);
        CP_COMMIT();
    }

    uint32_t af[2][4], bf[4][4];

    for (int it = 0; it < NT; it++) {
        CP_WAIT1();
        __syncthreads();

        const uint32_t so = (uint32_t)(it & 1) * G8_STAGE;
        #pragma unroll
        for (int ks = 0; ks < 4; ks++) {
            const uint32_t ko = so + (uint32_t)ks * 32;
            #pragma unroll
            for (int mf = 0; mf < 2; mf++)
                LDSM_X4(af[mf][0], af[mf][1], af[mf][2], af[mf][3], a_addr[mf] + ko);
            #pragma unroll
            for (int np = 0; np < 4; np++)
                LDSM_X4(bf[np][0], bf[np][1], bf[np][2], bf[np][3], b_addr[np] + ko);
            #pragma unroll
            for (int mf = 0; mf < 2; mf++)
                #pragma unroll
                for (int np = 0; np < 4; np++) {
                    mma_f16(acc[mf][2 * np + 0][0], acc[mf][2 * np + 0][1],
                            acc[mf][2 * np + 0][2], acc[mf][2 * np + 0][3],
                            af[mf][0], af[mf][1], af[mf][2], af[mf][3],
                            bf[np][0], bf[np][1]);
                    mma_f16(acc[mf][2 * np + 1][0], acc[mf][2 * np + 1][1],
                            acc[mf][2 * np + 1][2], acc[mf][2 * np + 1][3],
                            af[mf][0], af[mf][1], af[mf][2], af[mf][3],
                            bf[np][2], bf[np][3]);
                }
        }
        __syncthreads();

        if (it + 2 < NT) {
            const uint32_t o = (uint32_t)(it & 1) * G8_STAGE;
            stage_a(it + 2, o);
            const __half* Bn = Bb + (it + 2) * 64;
            #pragma unroll
            for (int j = 0; j < 8; j++)
                CP_ASYNC16(dB + o + j * (16 * ROW_B), Bn + (size_t)(j * 16) * ldb);
        }
        CP_COMMIT();
    }

    #pragma unroll
    for (int mf = 0; mf < 2; mf++) {
        #pragma unroll
        for (int nf = 0; nf < 8; nf++) {
            const int row = m_tile * 64 + wm + mf * 16 + g;
            const int col = n_tile * 128 + wn + nf * 8 + (tg << 1);
            *(__half2*)(C + (size_t)row * N + col) =
                __floats2half2_rn(acc[mf][nf][0], acc[mf][nf][1]);
            *(__half2*)(C + (size_t)(row + 8) * N + col) =
                __floats2half2_rn(acc[mf][nf][2], acc[mf][nf][3]);
        }
    }
}

// ---------------------------------------------------------------------------
// sim kernel (+batch offset): per (b,w,half) 128x128 QK^T, mask+1/W+relu^2.
// ---------------------------------------------------------------------------
__global__ __launch_bounds__(256, 2)
void attn_sim_kernel(const __half* __restrict__ qkv, __half* __restrict__ attnOut,
                     int batch0) {
    extern __shared__ __align__(128) char smem[];
    const uint32_t smem_base = smem_u32(smem);
    const int half_ = blockIdx.x, w = blockIdx.y, b = batch0 + blockIdx.z;

    const int tid  = threadIdx.x;
    const int warp = tid >> 5, lane = tid & 31;
    const int wm = (warp & 3) << 5;
    const int wn = (warp >> 2) << 6;
    const int g  = lane >> 2, tg = lane & 3;
    const int lr = tid >> 3;
    const int c4 = tid & 7;

    const int sel = lane >> 3;
    const int i8  = lane & 7;
    uint32_t a_addr[2], b_addr[4];
    #pragma unroll
    for (int mf = 0; mf < 2; mf++) {
        const int row = wm + 16 * mf + (sel & 1) * 8 + i8;
        a_addr[mf] = smem_base + (uint32_t)row * ROW_B + (sel >> 1) * 16;
    }
    #pragma unroll
    for (int np = 0; np < 4; np++) {
        const int row = wn + np * 16 + (sel >> 1) * 8 + i8;
        b_addr[np] = smem_base + SI_MAT_B + (uint32_t)row * ROW_B + (sel & 1) * 16;
    }

    const int kblk = (half_ == 0) ? (w > 0 ? w - 1 : 0) : w;
    const __half* Ab = qkv + (size_t)(b * SEQ + w * 128 + lr) * QKVN + c4 * 8;
    const __half* Bb = qkv + (size_t)(b * SEQ + kblk * 128 + lr) * QKVN + 2048 + c4 * 8;
    const uint32_t dA = smem_base + (uint32_t)lr * ROW_B + c4 * 16;
    const uint32_t dB = smem_base + SI_MAT_B + (uint32_t)lr * ROW_B + c4 * 16;

    float acc[2][8][4];
    #pragma unroll
    for (int i = 0; i < 2; i++)
        #pragma unroll
        for (int j = 0; j < 8; j++)
            #pragma unroll
            for (int q = 0; q < 4; q++) acc[i][j][q] = 0.f;

    const int NT = DIM >> 6;

    #pragma unroll
    for (int s = 0; s < 2; s++) {
        const uint32_t o = (uint32_t)s * SI_STAGE;
        const __half* An = Ab + s * 64;
        const __half* Bn = Bb + s * 64;
        #pragma unroll
        for (int j = 0; j < 4; j++) {
            CP_ASYNC16(dA + o + j * (32 * ROW_B), An + (size_t)(j * 32) * QKVN);
            CP_ASYNC16(dB + o + j * (32 * ROW_B), Bn + (size_t)(j * 32) * QKVN);
        }
        CP_COMMIT();
    }

    uint32_t af[2][4], bf[4][4];
    int s_cur = 0, s_nxt = 2;

    for (int it = 0; it < NT; it++) {
        CP_WAIT1();
        __syncthreads();

        if (it + 2 < NT) {
            const uint32_t o = (uint32_t)s_nxt * SI_STAGE;
            const __half* An = Ab + (it + 2) * 64;
            const __half* Bn = Bb + (it + 2) * 64;
            #pragma unroll
            for (int j = 0; j < 4; j++) {
                CP_ASYNC16(dA + o + j * (32 * ROW_B), An + (size_t)(j * 32) * QKVN);
                CP_ASYNC16(dB + o + j * (32 * ROW_B), Bn + (size_t)(j * 32) * QKVN);
            }
        }
        CP_COMMIT();

        const uint32_t so = (uint32_t)s_cur * SI_STAGE;
        #pragma unroll
        for (int ks = 0; ks < 4; ks++) {
            const uint32_t ko = so + (uint32_t)ks * 32;
            #pragma unroll
            for (int mf = 0; mf < 2; mf++)
                LDSM_X4(af[mf][0], af[mf][1], af[mf][2], af[mf][3], a_addr[mf] + ko);
            #pragma unroll
            for (int np = 0; np < 4; np++)
                LDSM_X4(bf[np][0], bf[np][1], bf[np][2], bf[np][3], b_addr[np] + ko);
            #pragma unroll
            for (int mf = 0; mf < 2; mf++)
                #pragma unroll
                for (int np = 0; np < 4; np++) {
                    mma_f16(acc[mf][2 * np + 0][0], acc[mf][2 * np + 0][1],
                            acc[mf][2 * np + 0][2], acc[mf][2 * np + 0][3],
                            af[mf][0], af[mf][1], af[mf][2], af[mf][3],
                            bf[np][0], bf[np][1]);
                    mma_f16(acc[mf][2 * np + 1][0], acc[mf][2 * np + 1][1],
                            acc[mf][2 * np + 1][2], acc[mf][2 * np + 1][3],
                            af[mf][0], af[mf][1], af[mf][2], af[mf][3],
                            bf[np][2], bf[np][3]);
                }
        }
        s_cur = (s_cur == 2) ? 0 : s_cur + 1;
        s_nxt = (s_nxt == 2) ? 0 : s_nxt + 1;
    }

    const bool halfvalid = (half_ == 1) || (w > 0);
    const float inv_w = 1.0f / (float)WIN;
    __half* Cb = attnOut + ((size_t)(b * NBLK + w) * 128) * 256 + half_ * 128;

    #pragma unroll
    for (int mf = 0; mf < 2; mf++) {
        #pragma unroll
        for (int nf = 0; nf < 8; nf++) {
            const int qi0 = wm + mf * 16 + g;
            const int kj  = wn + nf * 8 + (tg << 1);
            #pragma unroll
            for (int rr = 0; rr < 2; rr++) {
                const int qi = qi0 + rr * 8;
                float s0 = acc[mf][nf][rr * 2 + 0] * inv_w;
                float s1 = acc[mf][nf][rr * 2 + 1] * inv_w;
                bool k0 = halfvalid && ((half_ == 0) ? (qi <= kj)     : (qi >= kj));
                bool k1 = halfvalid && ((half_ == 0) ? (qi <= kj + 1) : (qi >= kj + 1));
                float r0 = k0 ? fmaxf(s0, 0.f) : 0.f;
                float r1 = k1 ? fmaxf(s1, 0.f) : 0.f;
                *(__half2*)(Cb + (size_t)qi * 256 + kj) =
                    __floats2half2_rn(r0 * r0, r1 * r1);
            }
        }
    }
}

// ---------------------------------------------------------------------------
// PV kernel (R12 body + batch-offset param).
// ---------------------------------------------------------------------------
__global__ __launch_bounds__(256, 2)
void attn_pv_kernel(const __half* __restrict__ qkv, const __half* __restrict__ attn,
                    __half* __restrict__ ao, int b0) {
    extern __shared__ __align__(128) char smem[];
    const uint32_t smem_base = smem_u32(smem);
    const int nb = blockIdx.x * 128, w = blockIdx.y, b = b0 + blockIdx.z;

    const int tid  = threadIdx.x;
    const int warp = tid >> 5, lane = tid & 31;
    const int wm = (warp & 3) << 5;
    const int wn = (warp >> 2) << 6;
    const int g  = lane >> 2, tg = lane & 3;

    const int ar  = tid >> 2;
    const int ac  = tid & 3;
    const int vr  = tid >> 3;
    const int vcc = tid & 7;

    const int sel = lane >> 3;
    const int i8  = lane & 7;
    uint32_t a_addr[2];
    #pragma unroll
    for (int mf = 0; mf < 2; mf++) {
        const int row = wm + 16 * mf + (sel & 1) * 8 + i8;
        a_addr[mf] = smem_base + (uint32_t)row * PV_ROWA + (sel >> 1) * 16;
    }
    uint32_t b_addr[4];
    #pragma unroll
    for (int np = 0; np < 4; np++) {
        b_addr[np] = smem_base + PV_AMAT
                   + (uint32_t)((sel & 1) * 8 + i8) * PV_ROWV
                   + (uint32_t)(wn + 16 * np + (sel >> 1) * 8) * 2;
    }

    const int prevblk = (w > 0) ? w - 1 : 0;
    const __half* Ag = attn + ((size_t)(b * NBLK + w) * 128 + ar) * 256 + ac * 8;
    const uint32_t dA = smem_base + (uint32_t)ar * PV_ROWA + ac * 16;
    const uint32_t dV = smem_base + PV_AMAT + (uint32_t)vr * PV_ROWV + vcc * 16;

    float acc[2][8][4];
    #pragma unroll
    for (int i = 0; i < 2; i++)
        #pragma unroll
        for (int j = 0; j < 8; j++)
            #pragma unroll
            for (int q = 0; q < 4; q++) acc[i][j][q] = 0.f;

    auto vptr = [&](int it) -> const __half* {
        const int kk = it * 32 + vr;
        const int tok = (kk < 128) ? (b * SEQ + prevblk * 128 + kk)
                                   : (b * SEQ + w * 128 + kk - 128);
        return qkv + (size_t)tok * QKVN + 4096 + nb;
    };

    #pragma unroll
    for (int s = 0; s < 2; s++) {
        const uint32_t o = (uint32_t)s * PV_STG;
        #pragma unroll
        for (int j = 0; j < 2; j++)
            CP_ASYNC16(dA + o + j * (64 * PV_ROWA), Ag + (size_t)(j * 64) * 256 + s * 32);
        const __half* vp = vptr(s);
        CP_ASYNC16(dV + o,       vp + vcc * 8);
        CP_ASYNC16(dV + o + 128, vp + (vcc + 8) * 8);
        CP_COMMIT();
    }

    uint32_t af[2][4], bf[4][4];
    int s_cur = 0, s_nxt = 2;

    for (int it = 0; it < 8; it++) {
        CP_WAIT1();
        __syncthreads();

        if (it + 2 < 8) {
            const uint32_t o = (uint32_t)s_nxt * PV_STG;
            #pragma unroll
            for (int j = 0; j < 2; j++)
                CP_ASYNC16(dA + o + j * (64 * PV_ROWA),
                           Ag + (size_t)(j * 64) * 256 + (it + 2) * 32);
            const __half* vp = vptr(it + 2);
            CP_ASYNC16(dV + o,       vp + vcc * 8);
            CP_ASYNC16(dV + o + 128, vp + (vcc + 8) * 8);
        }
        CP_COMMIT();

        const uint32_t so = (uint32_t)s_cur * PV_STG;
        #pragma unroll
        for (int ks = 0; ks < 2; ks++) {
            const uint32_t koA = so + (uint32_t)ks * 32;
            const uint32_t koB = so + (uint32_t)ks * (16 * PV_ROWV);
            #pragma unroll
            for (int mf = 0; mf < 2; mf++)
                LDSM_X4(af[mf][0], af[mf][1], af[mf][2], af[mf][3], a_addr[mf] + koA);
            #pragma unroll
            for (int np = 0; np < 4; np++)
                LDSM_X4T(bf[np][0], bf[np][1], bf[np][2], bf[np][3], b_addr[np] + koB);
            #pragma unroll
            for (int mf = 0; mf < 2; mf++)
                #pragma unroll
                for (int np = 0; np < 4; np++) {
                    mma_f16(acc[mf][2 * np + 0][0], acc[mf][2 * np + 0][1],
                            acc[mf][2 * np + 0][2], acc[mf][2 * np + 0][3],
                            af[mf][0], af[mf][1], af[mf][2], af[mf][3],
                            bf[np][0], bf[np][1]);
                    mma_f16(acc[mf][2 * np + 1][0], acc[mf][2 * np + 1][1],
                            acc[mf][2 * np + 1][2], acc[mf][2 * np + 1][3],
                            af[mf][0], af[mf][1], af[mf][2], af[mf][3],
                            bf[np][2], bf[np][3]);
                }
        }
        s_cur = (s_cur == 2) ? 0 : s_cur + 1;
        s_nxt = (s_nxt == 2) ? 0 : s_nxt + 1;
    }

    #pragma unroll
    for (int mf = 0; mf < 2; mf++) {
        #pragma unroll
        for (int nf = 0; nf < 8; nf++) {
            const int row = b * SEQ + w * 128 + wm + mf * 16 + g;
            const int col = nb + wn + nf * 8 + (tg << 1);
            *(__half2*)(ao + (size_t)row * DIM + col) =
                __floats2half2_rn(acc[mf][nf][0], acc[mf][nf][1]);
            *(__half2*)(ao + (size_t)(row + 8) * DIM + col) =
                __floats2half2_rn(acc[mf][nf][2], acc[mf][nf][3]);
        }
    }
}

// ---------------------------------------------------------------------------
// fp32 -> fp16 convert (weights only now)
// ---------------------------------------------------------------------------
__global__ __launch_bounds__(256)
void to_half_kernel(const float4* __restrict__ in, __half2* __restrict__ out, int n4) {
    int i = blockIdx.x * blockDim.x + threadIdx.x;
    if (i < n4) {
        float4 v = in[i];
        out[2 * i + 0] = __floats2half2_rn(v.x, v.y);
        out[2 * i + 1] = __floats2half2_rn(v.z, v.w);
    }
}

// ---------------------------------------------------------------------------
// launch
// ---------------------------------------------------------------------------
extern "C" void kernel_launch(void* const* d_in, const int* in_sizes, int n_in,
                              void* d_out, int out_size) {
    const float* x      = (const float*)d_in[0];
    const float* w_attn = (const float*)d_in[1];
    const float* w_o    = (const float*)d_in[2];
    float* out = (float*)d_out;

    __half *qkv, *attn, *ao, *wah, *woh;
    cudaGetSymbolAddress((void**)&qkv, g_qkv);
    cudaGetSymbolAddress((void**)&attn, g_attn);
    cudaGetSymbolAddress((void**)&ao, g_ao);
    cudaGetSymbolAddress((void**)&wah, g_wah);
    cudaGetSymbolAddress((void**)&woh, g_woh);

    // One-time stream/event creation (R14-proven leak-free pattern).
    static cudaStream_t s2 = nullptr, s3 = nullptr;
    static cudaEvent_t e0, eQ, eV, eS, eB, eC;
    if (!s2) {
        cudaStreamCreateWithFlags(&s2, cudaStreamNonBlocking);
        cudaStreamCreateWithFlags(&s3, cudaStreamNonBlocking);
        cudaEventCreateWithFlags(&e0, cudaEventDisableTiming);
        cudaEventCreateWithFlags(&eQ, cudaEventDisableTiming);
        cudaEventCreateWithFlags(&eV, cudaEventDisableTiming);
        cudaEventCreateWithFlags(&eS, cudaEventDisableTiming);
        cudaEventCreateWithFlags(&eB, cudaEventDisableTiming);
        cudaEventCreateWithFlags(&eC, cudaEventDisableTiming);
        cudaFuncSetAttribute(gemm_h_kernel,
                             cudaFuncAttributeMaxDynamicSharedMemorySize, G8_SMEM);
        cudaFuncSetAttribute(gemm_h32a_kernel,
                             cudaFuncAttributeMaxDynamicSharedMemorySize, G8_SMEM);
        cudaFuncSetAttribute(attn_sim_kernel,
                             cudaFuncAttributeMaxDynamicSharedMemorySize, SI_SMEM);
        cudaFuncSetAttribute(attn_pv_kernel,
                             cudaFuncAttributeMaxDynamicSharedMemorySize, PV_SMEM);
    }

    const int nwa = (QKVN * DIM) / 4;
    const int nwo = (DIM * DIM) / 4;

    // s0: convert w_attn (critical); s2: w_o (hidden under qk-gemm)
    to_half_kernel<<<(nwa + 255) / 256, 256>>>(
        (const float4*)w_attn, (__half2*)wah, nwa);
    cudaEventRecord(e0, 0);
    cudaStreamWaitEvent(s2, e0, 0);
    to_half_kernel<<<(nwo + 255) / 256, 256, 0, s2>>>(
        (const float4*)w_o, (__half2*)woh, nwo);

    // s0: qk-gemm (A = fp32 x, converted in-kernel)
    gemm_h32a_kernel<<<dim3(ROWS / 64, 4096 / 128), 128, G8_SMEM>>>(
        x, wah, qkv, DIM, DIM, QKVN, DIM);
    cudaEventRecord(eQ, 0);

    // fork: v-gemm on s2, sim on s0
    cudaStreamWaitEvent(s2, eQ, 0);
    gemm_h32a_kernel<<<dim3(ROWS / 64, 2048 / 128), 128, G8_SMEM, s2>>>(
        x, wah + (size_t)4096 * DIM, qkv + 4096, DIM, DIM, QKVN, DIM);
    attn_sim_kernel<<<dim3(2, NBLK, BATCH), 256, SI_SMEM>>>(qkv, attn, 0);
    cudaEventRecord(eS, 0);          // sim done
    cudaEventRecord(eV, s2);         // v done

    // PV batch 0 on s0 (needs sim [in-order] + v [eV])
    cudaStreamWaitEvent(0, eV, 0);
    attn_pv_kernel<<<dim3(DIM / 128, NBLK, 1), 256, PV_SMEM>>>(qkv, attn, ao, 0);
    // PV batch 1 on s2 (in-order after v; needs sim [eS])
    cudaStreamWaitEvent(s2, eS, 0);
    attn_pv_kernel<<<dim3(DIM / 128, NBLK, 1), 256, PV_SMEM, s2>>>(qkv, attn, ao, 1);
    cudaEventRecord(eB, s2);

    // gemm2 batch 0 on s0 (in-order after PV b0); co-resident with PV b1
    gemm_h_kernel<<<dim3(SEQ / 64, DIM / 128), 128, G8_SMEM>>>(
        ao, woh, out, DIM, DIM, DIM, DIM, 0);
    // gemm2 batch 1 on s3 (after PV b1)
    cudaStreamWaitEvent(s3, eB, 0);
    gemm_h_kernel<<<dim3(SEQ / 64, DIM / 128), 128, G8_SMEM, s3>>>(
        ao + (size_t)SEQ * DIM, woh, out + (size_t)SEQ * DIM, DIM, DIM, DIM, DIM, 0);
    cudaEventRecord(eC, s3);
    cudaStreamWaitEvent(0, eC, 0);
}

// round 17
// speedup vs baseline: 1.9099x; 1.9099x over previous
#include <cuda_runtime.h>
#include <cuda_fp16.h>
#include <cstdint>

// Problem constants: B=2, T=8192, D=2048, W=128
#define BATCH 2
#define SEQ   8192
#define DIM   2048
#define WIN   128
#define NBLK  64
#define ROWS  16384
#define QKVN  6144

// Scratch (device globals: the sanctioned alloc-free workaround)
__device__ __half g_qkv[(size_t)ROWS * QKVN];
__device__ __half g_attn[(size_t)BATCH * NBLK * 128 * 256];
__device__ __half g_ao[(size_t)ROWS * DIM];
__device__ __half g_xh[(size_t)ROWS * DIM];
__device__ __half g_wah[(size_t)QKVN * DIM];
__device__ __half g_woh[(size_t)DIM * DIM];

// ---------------------------------------------------------------------------
// helpers
// ---------------------------------------------------------------------------
__device__ __forceinline__ uint32_t smem_u32(const void* p) {
    uint32_t a;
    asm("{ .reg .u64 t; cvta.to.shared.u64 t, %1; cvt.u32.u64 %0, t; }" : "=r"(a) : "l"(p));
    return a;
}

__device__ __forceinline__ void mma_f16(float& d0, float& d1, float& d2, float& d3,
                                        uint32_t a0, uint32_t a1, uint32_t a2, uint32_t a3,
                                        uint32_t b0, uint32_t b1) {
    asm volatile(
        "mma.sync.aligned.m16n8k16.row.col.f32.f16.f16.f32 "
        "{%0,%1,%2,%3}, {%4,%5,%6,%7}, {%8,%9}, {%0,%1,%2,%3};\n"
        : "+f"(d0), "+f"(d1), "+f"(d2), "+f"(d3)
        : "r"(a0), "r"(a1), "r"(a2), "r"(a3), "r"(b0), "r"(b1));
}

#define LDSM_X4(r0, r1, r2, r3, addr)                                          \
    asm volatile("ldmatrix.sync.aligned.m8n8.x4.shared.b16 {%0,%1,%2,%3}, [%4];" \
                 : "=r"(r0), "=r"(r1), "=r"(r2), "=r"(r3) : "r"(addr))
#define LDSM_X4T(r0, r1, r2, r3, addr)                                         \
    asm volatile("ldmatrix.sync.aligned.m8n8.x4.trans.shared.b16 {%0,%1,%2,%3}, [%4];" \
                 : "=r"(r0), "=r"(r1), "=r"(r2), "=r"(r3) : "r"(addr))

#define CP_ASYNC16(dst, src)                                                   \
    asm volatile("cp.async.cg.shared.global [%0], [%1], 16;"                   \
                 :: "r"(dst), "l"(src) : "memory")
#define CP_COMMIT() asm volatile("cp.async.commit_group;" ::: "memory")
#define CP_WAIT1()  asm volatile("cp.async.wait_group 1;" ::: "memory")

// ---------------------------------------------------------------------------
// GEMM geometry (R8, proven best): CTA 64x128, K-tile 64, 2 stages, 4 CTAs/SM.
#define ROW_B     144
#define G8_MAT_A  9216
#define G8_STAGE  27648
#define G8_SMEM   (2 * G8_STAGE)

// sim geometry: 128x128 tile, 3 stages
#define SI_MAT_B  18432
#define SI_STAGE  36864
#define SI_SMEM   (3 * SI_STAGE)

// PV geometry (R12): CTA 128(M) x 128(N), K-tile 32, 3 stages.
#define PV_ROWA   80
#define PV_AMAT   10240
#define PV_ROWV   272
#define PV_VMAT   8704
#define PV_STG    (PV_AMAT + PV_VMAT)
#define PV_SMEM   (3 * PV_STG)

// ---------------------------------------------------------------------------
// fp16 NT GEMM (proven): CTA 64x128, 4 warps, 2-stage, 4 CTAs/SM.
// ---------------------------------------------------------------------------
__global__ __launch_bounds__(128, 4)
void gemm_h_kernel(const __half* __restrict__ A, const __half* __restrict__ B,
                   void* __restrict__ Cout, int lda, int ldb, int N, int K,
                   int out_half) {
    extern __shared__ __align__(128) char smem[];
    const uint32_t smem_base = smem_u32(smem);

    const int m_tile = blockIdx.x;
    const int n_tile = blockIdx.y;

    const int tid  = threadIdx.x;
    const int warp = tid >> 5, lane = tid & 31;
    const int wm = (warp & 1) << 5;
    const int wn = (warp >> 1) << 6;
    const int g  = lane >> 2, tg = lane & 3;
    const int lr = tid >> 3;
    const int c4 = tid & 7;

    const int sel = lane >> 3;
    const int i8  = lane & 7;
    uint32_t a_addr[2], b_addr[4];
    #pragma unroll
    for (int mf = 0; mf < 2; mf++) {
        const int row = wm + 16 * mf + (sel & 1) * 8 + i8;
        a_addr[mf] = smem_base + (uint32_t)row * ROW_B + (sel >> 1) * 16;
    }
    #pragma unroll
    for (int np = 0; np < 4; np++) {
        const int row = wn + np * 16 + (sel >> 1) * 8 + i8;
        b_addr[np] = smem_base + G8_MAT_A + (uint32_t)row * ROW_B + (sel & 1) * 16;
    }

    const __half* Ab = A + (size_t)(m_tile * 64 + lr) * lda + c4 * 8;
    const __half* Bb = B + (size_t)(n_tile * 128 + lr) * ldb + c4 * 8;
    const uint32_t dA = smem_base + (uint32_t)lr * ROW_B + c4 * 16;
    const uint32_t dB = smem_base + G8_MAT_A + (uint32_t)lr * ROW_B + c4 * 16;

    float acc[2][8][4];
    #pragma unroll
    for (int i = 0; i < 2; i++)
        #pragma unroll
        for (int j = 0; j < 8; j++)
            #pragma unroll
            for (int q = 0; q < 4; q++) acc[i][j][q] = 0.f;

    const int NT = K >> 6;

    #pragma unroll
    for (int s = 0; s < 2; s++) {
        const uint32_t o = (uint32_t)s * G8_STAGE;
        const __half* An = Ab + s * 64;
        const __half* Bn = Bb + s * 64;
        #pragma unroll
        for (int j = 0; j < 4; j++)
            CP_ASYNC16(dA + o + j * (16 * ROW_B), An + (size_t)(j * 16) * lda);
        #pragma unroll
        for (int j = 0; j < 8; j++)
            CP_ASYNC16(dB + o + j * (16 * ROW_B), Bn + (size_t)(j * 16) * ldb);
        CP_COMMIT();
    }

    uint32_t af[2][4], bf[4][4];

    for (int it = 0; it < NT; it++) {
        CP_WAIT1();
        __syncthreads();

        const uint32_t so = (uint32_t)(it & 1) * G8_STAGE;
        #pragma unroll
        for (int ks = 0; ks < 4; ks++) {
            const uint32_t ko = so + (uint32_t)ks * 32;
            #pragma unroll
            for (int mf = 0; mf < 2; mf++)
                LDSM_X4(af[mf][0], af[mf][1], af[mf][2], af[mf][3], a_addr[mf] + ko);
            #pragma unroll
            for (int np = 0; np < 4; np++)
                LDSM_X4(bf[np][0], bf[np][1], bf[np][2], bf[np][3], b_addr[np] + ko);
            #pragma unroll
            for (int mf = 0; mf < 2; mf++)
                #pragma unroll
                for (int np = 0; np < 4; np++) {
                    mma_f16(acc[mf][2 * np + 0][0], acc[mf][2 * np + 0][1],
                            acc[mf][2 * np + 0][2], acc[mf][2 * np + 0][3],
                            af[mf][0], af[mf][1], af[mf][2], af[mf][3],
                            bf[np][0], bf[np][1]);
                    mma_f16(acc[mf][2 * np + 1][0], acc[mf][2 * np + 1][1],
                            acc[mf][2 * np + 1][2], acc[mf][2 * np + 1][3],
                            af[mf][0], af[mf][1], af[mf][2], af[mf][3],
                            bf[np][2], bf[np][3]);
                }
        }
        __syncthreads();

        if (it + 2 < NT) {
            const uint32_t o = (uint32_t)(it & 1) * G8_STAGE;
            const __half* An = Ab + (it + 2) * 64;
            const __half* Bn = Bb + (it + 2) * 64;
            #pragma unroll
            for (int j = 0; j < 4; j++)
                CP_ASYNC16(dA + o + j * (16 * ROW_B), An + (size_t)(j * 16) * lda);
            #pragma unroll
            for (int j = 0; j < 8; j++)
                CP_ASYNC16(dB + o + j * (16 * ROW_B), Bn + (size_t)(j * 16) * ldb);
        }
        CP_COMMIT();
    }

    #pragma unroll
    for (int mf = 0; mf < 2; mf++) {
        #pragma unroll
        for (int nf = 0; nf < 8; nf++) {
            const int row = m_tile * 64 + wm + mf * 16 + g;
            const int col = n_tile * 128 + wn + nf * 8 + (tg << 1);
            if (out_half) {
                __half* C = (__half*)Cout;
                *(__half2*)(C + (size_t)row * N + col) =
                    __floats2half2_rn(acc[mf][nf][0], acc[mf][nf][1]);
                *(__half2*)(C + (size_t)(row + 8) * N + col) =
                    __floats2half2_rn(acc[mf][nf][2], acc[mf][nf][3]);
            } else {
                float* C = (float*)Cout;
                *(float2*)(C + (size_t)row * N + col) =
                    make_float2(acc[mf][nf][0], acc[mf][nf][1]);
                *(float2*)(C + (size_t)(row + 8) * N + col) =
                    make_float2(acc[mf][nf][2], acc[mf][nf][3]);
            }
        }
    }
}

// ---------------------------------------------------------------------------
// sim kernel (proven): per (b,w,half) 128x128 QK^T, mask+1/W+relu^2 -> fp16.
// ---------------------------------------------------------------------------
__global__ __launch_bounds__(256, 2)
void attn_sim_kernel(const __half* __restrict__ qkv, __half* __restrict__ attnOut) {
    extern __shared__ __align__(128) char smem[];
    const uint32_t smem_base = smem_u32(smem);
    const int half_ = blockIdx.x, w = blockIdx.y, b = blockIdx.z;

    const int tid  = threadIdx.x;
    const int warp = tid >> 5, lane = tid & 31;
    const int wm = (warp & 3) << 5;
    const int wn = (warp >> 2) << 6;
    const int g  = lane >> 2, tg = lane & 3;
    const int lr = tid >> 3;
    const int c4 = tid & 7;

    const int sel = lane >> 3;
    const int i8  = lane & 7;
    uint32_t a_addr[2], b_addr[4];
    #pragma unroll
    for (int mf = 0; mf < 2; mf++) {
        const int row = wm + 16 * mf + (sel & 1) * 8 + i8;
        a_addr[mf] = smem_base + (uint32_t)row * ROW_B + (sel >> 1) * 16;
    }
    #pragma unroll
    for (int np = 0; np < 4; np++) {
        const int row = wn + np * 16 + (sel >> 1) * 8 + i8;
        b_addr[np] = smem_base + SI_MAT_B + (uint32_t)row * ROW_B + (sel & 1) * 16;
    }

    const int kblk = (half_ == 0) ? (w > 0 ? w - 1 : 0) : w;
    const __half* Ab = qkv + (size_t)(b * SEQ + w * 128 + lr) * QKVN + c4 * 8;
    const __half* Bb = qkv + (size_t)(b * SEQ + kblk * 128 + lr) * QKVN + 2048 + c4 * 8;
    const uint32_t dA = smem_base + (uint32_t)lr * ROW_B + c4 * 16;
    const uint32_t dB = smem_base + SI_MAT_B + (uint32_t)lr * ROW_B + c4 * 16;

    float acc[2][8][4];
    #pragma unroll
    for (int i = 0; i < 2; i++)
        #pragma unroll
        for (int j = 0; j < 8; j++)
            #pragma unroll
            for (int q = 0; q < 4; q++) acc[i][j][q] = 0.f;

    const int NT = DIM >> 6;

    #pragma unroll
    for (int s = 0; s < 2; s++) {
        const uint32_t o = (uint32_t)s * SI_STAGE;
        const __half* An = Ab + s * 64;
        const __half* Bn = Bb + s * 64;
        #pragma unroll
        for (int j = 0; j < 4; j++) {
            CP_ASYNC16(dA + o + j * (32 * ROW_B), An + (size_t)(j * 32) * QKVN);
            CP_ASYNC16(dB + o + j * (32 * ROW_B), Bn + (size_t)(j * 32) * QKVN);
        }
        CP_COMMIT();
    }

    uint32_t af[2][4], bf[4][4];
    int s_cur = 0, s_nxt = 2;

    for (int it = 0; it < NT; it++) {
        CP_WAIT1();
        __syncthreads();

        if (it + 2 < NT) {
            const uint32_t o = (uint32_t)s_nxt * SI_STAGE;
            const __half* An = Ab + (it + 2) * 64;
            const __half* Bn = Bb + (it + 2) * 64;
            #pragma unroll
            for (int j = 0; j < 4; j++) {
                CP_ASYNC16(dA + o + j * (32 * ROW_B), An + (size_t)(j * 32) * QKVN);
                CP_ASYNC16(dB + o + j * (32 * ROW_B), Bn + (size_t)(j * 32) * QKVN);
            }
        }
        CP_COMMIT();

        const uint32_t so = (uint32_t)s_cur * SI_STAGE;
        #pragma unroll
        for (int ks = 0; ks < 4; ks++) {
            const uint32_t ko = so + (uint32_t)ks * 32;
            #pragma unroll
            for (int mf = 0; mf < 2; mf++)
                LDSM_X4(af[mf][0], af[mf][1], af[mf][2], af[mf][3], a_addr[mf] + ko);
            #pragma unroll
            for (int np = 0; np < 4; np++)
                LDSM_X4(bf[np][0], bf[np][1], bf[np][2], bf[np][3], b_addr[np] + ko);
            #pragma unroll
            for (int mf = 0; mf < 2; mf++)
                #pragma unroll
                for (int np = 0; np < 4; np++) {
                    mma_f16(acc[mf][2 * np + 0][0], acc[mf][2 * np + 0][1],
                            acc[mf][2 * np + 0][2], acc[mf][2 * np + 0][3],
                            af[mf][0], af[mf][1], af[mf][2], af[mf][3],
                            bf[np][0], bf[np][1]);
                    mma_f16(acc[mf][2 * np + 1][0], acc[mf][2 * np + 1][1],
                            acc[mf][2 * np + 1][2], acc[mf][2 * np + 1][3],
                            af[mf][0], af[mf][1], af[mf][2], af[mf][3],
                            bf[np][2], bf[np][3]);
                }
        }
        s_cur = (s_cur == 2) ? 0 : s_cur + 1;
        s_nxt = (s_nxt == 2) ? 0 : s_nxt + 1;
    }

    const bool halfvalid = (half_ == 1) || (w > 0);
    const float inv_w = 1.0f / (float)WIN;
    __half* Cb = attnOut + ((size_t)(b * NBLK + w) * 128) * 256 + half_ * 128;

    #pragma unroll
    for (int mf = 0; mf < 2; mf++) {
        #pragma unroll
        for (int nf = 0; nf < 8; nf++) {
            const int qi0 = wm + mf * 16 + g;
            const int kj  = wn + nf * 8 + (tg << 1);
            #pragma unroll
            for (int rr = 0; rr < 2; rr++) {
                const int qi = qi0 + rr * 8;
                float s0 = acc[mf][nf][rr * 2 + 0] * inv_w;
                float s1 = acc[mf][nf][rr * 2 + 1] * inv_w;
                bool k0 = halfvalid && ((half_ == 0) ? (qi <= kj)     : (qi >= kj));
                bool k1 = halfvalid && ((half_ == 0) ? (qi <= kj + 1) : (qi >= kj + 1));
                float r0 = k0 ? fmaxf(s0, 0.f) : 0.f;
                float r1 = k1 ? fmaxf(s1, 0.f) : 0.f;
                *(__half2*)(Cb + (size_t)qi * 256 + kj) =
                    __floats2half2_rn(r0 * r0, r1 * r1);
            }
        }
    }
}

// ---------------------------------------------------------------------------
// PV kernel (R12 body + batch-offset param for chunked launch).
// ---------------------------------------------------------------------------
__global__ __launch_bounds__(256, 2)
void attn_pv_kernel(const __half* __restrict__ qkv, const __half* __restrict__ attn,
                    __half* __restrict__ ao, int b0) {
    extern __shared__ __align__(128) char smem[];
    const uint32_t smem_base = smem_u32(smem);
    const int nb = blockIdx.x * 128, w = blockIdx.y, b = b0 + blockIdx.z;

    const int tid  = threadIdx.x;
    const int warp = tid >> 5, lane = tid & 31;
    const int wm = (warp & 3) << 5;
    const int wn = (warp >> 2) << 6;
    const int g  = lane >> 2, tg = lane & 3;

    const int ar  = tid >> 2;
    const int ac  = tid & 3;
    const int vr  = tid >> 3;
    const int vcc = tid & 7;

    const int sel = lane >> 3;
    const int i8  = lane & 7;
    uint32_t a_addr[2];
    #pragma unroll
    for (int mf = 0; mf < 2; mf++) {
        const int row = wm + 16 * mf + (sel & 1) * 8 + i8;
        a_addr[mf] = smem_base + (uint32_t)row * PV_ROWA + (sel >> 1) * 16;
    }
    uint32_t b_addr[4];
    #pragma unroll
    for (int np = 0; np < 4; np++) {
        b_addr[np] = smem_base + PV_AMAT
                   + (uint32_t)((sel & 1) * 8 + i8) * PV_ROWV
                   + (uint32_t)(wn + 16 * np + (sel >> 1) * 8) * 2;
    }

    const int prevblk = (w > 0) ? w - 1 : 0;
    const __half* Ag = attn + ((size_t)(b * NBLK + w) * 128 + ar) * 256 + ac * 8;
    const uint32_t dA = smem_base + (uint32_t)ar * PV_ROWA + ac * 16;
    const uint32_t dV = smem_base + PV_AMAT + (uint32_t)vr * PV_ROWV + vcc * 16;

    float acc[2][8][4];
    #pragma unroll
    for (int i = 0; i < 2; i++)
        #pragma unroll
        for (int j = 0; j < 8; j++)
            #pragma unroll
            for (int q = 0; q < 4; q++) acc[i][j][q] = 0.f;

    auto vptr = [&](int it) -> const __half* {
        const int kk = it * 32 + vr;
        const int tok = (kk < 128) ? (b * SEQ + prevblk * 128 + kk)
                                   : (b * SEQ + w * 128 + kk - 128);
        return qkv + (size_t)tok * QKVN + 4096 + nb;
    };

    #pragma unroll
    for (int s = 0; s < 2; s++) {
        const uint32_t o = (uint32_t)s * PV_STG;
        #pragma unroll
        for (int j = 0; j < 2; j++)
            CP_ASYNC16(dA + o + j * (64 * PV_ROWA), Ag + (size_t)(j * 64) * 256 + s * 32);
        const __half* vp = vptr(s);
        CP_ASYNC16(dV + o,       vp + vcc * 8);
        CP_ASYNC16(dV + o + 128, vp + (vcc + 8) * 8);
        CP_COMMIT();
    }

    uint32_t af[2][4], bf[4][4];
    int s_cur = 0, s_nxt = 2;

    for (int it = 0; it < 8; it++) {
        CP_WAIT1();
        __syncthreads();

        if (it + 2 < 8) {
            const uint32_t o = (uint32_t)s_nxt * PV_STG;
            #pragma unroll
            for (int j = 0; j < 2; j++)
                CP_ASYNC16(dA + o + j * (64 * PV_ROWA),
                           Ag + (size_t)(j * 64) * 256 + (it + 2) * 32);
            const __half* vp = vptr(it + 2);
            CP_ASYNC16(dV + o,       vp + vcc * 8);
            CP_ASYNC16(dV + o + 128, vp + (vcc + 8) * 8);
        }
        CP_COMMIT();

        const uint32_t so = (uint32_t)s_cur * PV_STG;
        #pragma unroll
        for (int ks = 0; ks < 2; ks++) {
            const uint32_t koA = so + (uint32_t)ks * 32;
            const uint32_t koB = so + (uint32_t)ks * (16 * PV_ROWV);
            #pragma unroll
            for (int mf = 0; mf < 2; mf++)
                LDSM_X4(af[mf][0], af[mf][1], af[mf][2], af[mf][3], a_addr[mf] + koA);
            #pragma unroll
            for (int np = 0; np < 4; np++)
                LDSM_X4T(bf[np][0], bf[np][1], bf[np][2], bf[np][3], b_addr[np] + koB);
            #pragma unroll
            for (int mf = 0; mf < 2; mf++)
                #pragma unroll
                for (int np = 0; np < 4; np++) {
                    mma_f16(acc[mf][2 * np + 0][0], acc[mf][2 * np + 0][1],
                            acc[mf][2 * np + 0][2], acc[mf][2 * np + 0][3],
                            af[mf][0], af[mf][1], af[mf][2], af[mf][3],
                            bf[np][0], bf[np][1]);
                    mma_f16(acc[mf][2 * np + 1][0], acc[mf][2 * np + 1][1],
                            acc[mf][2 * np + 1][2], acc[mf][2 * np + 1][3],
                            af[mf][0], af[mf][1], af[mf][2], af[mf][3],
                            bf[np][2], bf[np][3]);
                }
        }
        s_cur = (s_cur == 2) ? 0 : s_cur + 1;
        s_nxt = (s_nxt == 2) ? 0 : s_nxt + 1;
    }

    #pragma unroll
    for (int mf = 0; mf < 2; mf++) {
        #pragma unroll
        for (int nf = 0; nf < 8; nf++) {
            const int row = b * SEQ + w * 128 + wm + mf * 16 + g;
            const int col = nb + wn + nf * 8 + (tg << 1);
            *(__half2*)(ao + (size_t)row * DIM + col) =
                __floats2half2_rn(acc[mf][nf][0], acc[mf][nf][1]);
            *(__half2*)(ao + (size_t)(row + 8) * DIM + col) =
                __floats2half2_rn(acc[mf][nf][2], acc[mf][nf][3]);
        }
    }
}

// ---------------------------------------------------------------------------
// fp32 -> fp16 converts
// ---------------------------------------------------------------------------
__global__ __launch_bounds__(256)
void convert_xw_kernel(const float4* __restrict__ x,  __half2* __restrict__ xh,  int nx,
                       const float4* __restrict__ wa, __half2* __restrict__ wah, int nwa) {
    int i = blockIdx.x * blockDim.x + threadIdx.x;
    const float4* src;
    __half2* dst;
    int j;
    if (i < nx)            { src = x;  dst = xh;  j = i; }
    else if (i < nx + nwa) { src = wa; dst = wah; j = i - nx; }
    else return;
    float4 v = src[j];
    dst[2 * j + 0] = __floats2half2_rn(v.x, v.y);
    dst[2 * j + 1] = __floats2half2_rn(v.z, v.w);
}

__global__ __launch_bounds__(256)
void to_half_kernel(const float4* __restrict__ in, __half2* __restrict__ out, int n4) {
    int i = blockIdx.x * blockDim.x + threadIdx.x;
    if (i < n4) {
        float4 v = in[i];
        out[2 * i + 0] = __floats2half2_rn(v.x, v.y);
        out[2 * i + 1] = __floats2half2_rn(v.z, v.w);
    }
}

// ---------------------------------------------------------------------------
// launch (R14 schedule, verified best: 1604.0 us)
// ---------------------------------------------------------------------------
extern "C" void kernel_launch(void* const* d_in, const int* in_sizes, int n_in,
                              void* d_out, int out_size) {
    const float* x      = (const float*)d_in[0];
    const float* w_attn = (const float*)d_in[1];
    const float* w_o    = (const float*)d_in[2];
    float* out = (float*)d_out;

    __half *qkv, *attn, *ao, *xh, *wah, *woh;
    cudaGetSymbolAddress((void**)&qkv, g_qkv);
    cudaGetSymbolAddress((void**)&attn, g_attn);
    cudaGetSymbolAddress((void**)&ao, g_ao);
    cudaGetSymbolAddress((void**)&xh, g_xh);
    cudaGetSymbolAddress((void**)&wah, g_wah);
    cudaGetSymbolAddress((void**)&woh, g_woh);

    // One-time stream/event creation (R14-proven leak-free pattern).
    static cudaStream_t s2 = nullptr, s3 = nullptr;
    static cudaEvent_t e0, e1, e2, eS, eB, eC;
    if (!s2) {
        cudaStreamCreateWithFlags(&s2, cudaStreamNonBlocking);
        cudaStreamCreateWithFlags(&s3, cudaStreamNonBlocking);
        cudaEventCreateWithFlags(&e0, cudaEventDisableTiming);
        cudaEventCreateWithFlags(&e1, cudaEventDisableTiming);
        cudaEventCreateWithFlags(&e2, cudaEventDisableTiming);
        cudaEventCreateWithFlags(&eS, cudaEventDisableTiming);
        cudaEventCreateWithFlags(&eB, cudaEventDisableTiming);
        cudaEventCreateWithFlags(&eC, cudaEventDisableTiming);
        cudaFuncSetAttribute(gemm_h_kernel,
                             cudaFuncAttributeMaxDynamicSharedMemorySize, G8_SMEM);
        cudaFuncSetAttribute(attn_sim_kernel,
                             cudaFuncAttributeMaxDynamicSharedMemorySize, SI_SMEM);
        cudaFuncSetAttribute(attn_pv_kernel,
                             cudaFuncAttributeMaxDynamicSharedMemorySize, PV_SMEM);
    }

    // convert x + w_attn (needed by gemm1); w_o convert hides on s2
    {
        const int nx  = ROWS * DIM / 4;
        const int nwa = QKVN * DIM / 4;
        convert_xw_kernel<<<(nx + nwa + 255) / 256, 256>>>(
            (const float4*)x, (__half2*)xh, nx,
            (const float4*)w_attn, (__half2*)wah, nwa);
    }
    cudaEventRecord(e0, 0);
    cudaStreamWaitEvent(s2, e0, 0);
    {
        const int nwo = DIM * DIM / 4;
        to_half_kernel<<<(nwo + 255) / 256, 256, 0, s2>>>(
            (const float4*)w_o, (__half2*)woh, nwo);
    }

    // qk-part of qkv: columns 0..4095 (stream 0)
    gemm_h_kernel<<<dim3(ROWS / 64, 4096 / 128), 128, G8_SMEM>>>(
        xh, wah, qkv, DIM, DIM, QKVN, DIM, 1);

    // fork: v-part of qkv on s2, sim on stream 0
    cudaEventRecord(e1, 0);
    cudaStreamWaitEvent(s2, e1, 0);
    gemm_h_kernel<<<dim3(ROWS / 64, 2048 / 128), 128, G8_SMEM, s2>>>(
        xh, wah + (size_t)4096 * DIM, qkv + 4096, DIM, DIM, QKVN, DIM, 1);
    attn_sim_kernel<<<dim3(2, NBLK, BATCH), 256, SI_SMEM>>>(qkv, attn);
    cudaEventRecord(eS, 0);          // sim done
    cudaEventRecord(e2, s2);         // v done

    // PV batch 0 on stream 0 (needs sim [in-order] + v [e2])
    cudaStreamWaitEvent(0, e2, 0);
    attn_pv_kernel<<<dim3(DIM / 128, NBLK, 1), 256, PV_SMEM>>>(qkv, attn, ao, 0);
    // PV batch 1 on s2 (needs v [in-order] + sim [eS])
    cudaStreamWaitEvent(s2, eS, 0);
    attn_pv_kernel<<<dim3(DIM / 128, NBLK, 1), 256, PV_SMEM, s2>>>(qkv, attn, ao, 1);
    cudaEventRecord(eB, s2);

    // gemm2 batch 0 on stream 0 (in-order after PV b=0); co-resident with PV b=1
    gemm_h_kernel<<<dim3(SEQ / 64, DIM / 128), 128, G8_SMEM>>>(
        ao, woh, out, DIM, DIM, DIM, DIM, 0);
    // gemm2 batch 1 on s3 (after PV b=1)
    cudaStreamWaitEvent(s3, eB, 0);
    gemm_h_kernel<<<dim3(SEQ / 64, DIM / 128), 128, G8_SMEM, s3>>>(
        ao + (size_t)SEQ * DIM, woh, out + (size_t)SEQ * DIM, DIM, DIM, DIM, DIM, 0);
    cudaEventRecord(eC, s3);
    cudaStreamWaitEvent(0, eC, 0);
}